// round 16
// baseline (speedup 1.0000x reference)
#include <cuda_runtime.h>
#include <cuda_fp16.h>
#include <cstdint>

// ============================================================================
// FeedForwardQuantum: x[4,4096,1024], W1[4096,1024], W2[1024,4096]
//   q   = cos(x)*cos(theta)          [M=16384, 1024]  fp16 (pre-swizzled tiles)
//   h   = relu(q @ W1^T)             [M, 4096]        fp16 (pre-swizzled tiles)
//   out = h @ W2^T                   [M, 1024]        fp32 row-major
//
// Plain-sm_100 tensor path: mma.sync.m16n8k16 + ldmatrix + cp.async pipeline.
// R16 = R15 with ONE change: STAGES 2->3 (prefetch depth 1->2, CP_WAIT(1)).
//   BM=64, BN=128, 128-thr CTAs (4 warps, 2m x 2n, warp tile 32x64),
//   3 stages x 24KB = 72KB/CTA -> 3 CTAs/SM (12 warps, 3 barrier domains).
//   A/B test vs R13 (12w/d1/64x64: 75.5%) and R15 (16w/d1/32x64: 76.2%):
//   isolates prefetch depth as the variable.
//
// Staging layout (fp16, GMEM): [K/64 chunks][rows][64 halves], 128B-swizzle
// XOR applied at write time:
//     half_index(row, k) = ((k>>6)*R + row)*64 + ((k&63) ^ ((row&7)<<3))
// ============================================================================
static constexpr int M_TOK = 16384;
static constexpr int DDIM  = 1024;
static constexpr int FDIM  = 4096;

static constexpr int BM = 64;
static constexpr int BN = 128;
static constexpr int BK = 64;          // 64 halves = 128B rows
static constexpr int STAGES = 3;
static constexpr int THREADS = 128;    // 4 warps, grid 2(m) x 2(n), tile 32x64

static constexpr int A_BYTES     = BM * 128;             // 8192
static constexpr int B_BYTES     = BN * 128;             // 16384
static constexpr int STAGE_BYTES = A_BYTES + B_BYTES;    // 24576
static constexpr int SMEM_TOTAL  = STAGES * STAGE_BYTES; // 73728

// ---- scratch (device globals; no runtime allocation allowed) ----
__device__ __half g_q [16777216];   // q  tiled/swizzled  [1024/64][16384][64]
__device__ __half g_w1[ 4194304];   // W1 tiled/swizzled  [1024/64][4096 ][64]
__device__ __half g_w2[ 4194304];   // W2 tiled/swizzled  [4096/64][1024 ][64]
__device__ __half g_h [67108864];   // h  tiled/swizzled  [4096/64][16384][64]

// ============================================================================
// PTX helpers
// ============================================================================
__device__ __forceinline__ uint32_t smem_u32(const void* p) {
    uint32_t a;
    asm("{ .reg .u64 t; cvta.to.shared.u64 t, %1; cvt.u32.u64 %0, t; }"
        : "=r"(a) : "l"(p));
    return a;
}

__device__ __forceinline__ void cp_async16(uint32_t dst, const void* src) {
    asm volatile("cp.async.cg.shared.global [%0], [%1], 16;"
                 :: "r"(dst), "l"(src) : "memory");
}
#define CP_COMMIT() asm volatile("cp.async.commit_group;" ::: "memory")
#define CP_WAIT(n)  asm volatile("cp.async.wait_group %0;" :: "n"(n) : "memory")

__device__ __forceinline__ void ldsm_x4(uint32_t& r0, uint32_t& r1,
                                        uint32_t& r2, uint32_t& r3,
                                        uint32_t addr) {
    asm volatile("ldmatrix.sync.aligned.m8n8.x4.shared.b16 {%0,%1,%2,%3}, [%4];"
                 : "=r"(r0), "=r"(r1), "=r"(r2), "=r"(r3) : "r"(addr));
}

__device__ __forceinline__ void mma16816(float* d, const uint32_t* a,
                                         const uint32_t* b) {
    asm volatile(
        "mma.sync.aligned.m16n8k16.row.col.f32.f16.f16.f32 "
        "{%0,%1,%2,%3}, {%4,%5,%6,%7}, {%8,%9}, {%0,%1,%2,%3};"
        : "+f"(d[0]), "+f"(d[1]), "+f"(d[2]), "+f"(d[3])
        : "r"(a[0]), "r"(a[1]), "r"(a[2]), "r"(a[3]), "r"(b[0]), "r"(b[1]));
}

// ============================================================================
// Conversion kernels: fp32 -> fp16 directly into the swizzled tiled layout
// ============================================================================
__global__ void cvt_q_kernel(const float4* __restrict__ x,
                             const float*  __restrict__ theta,
                             __half*       __restrict__ q) {
    size_t i4 = (size_t)blockIdx.x * blockDim.x + threadIdx.x;
    size_t i  = i4 * 4;
    int    k  = (int)(i & (DDIM - 1));
    size_t m  = i >> 10;
    float4 v  = x[i4];
    float c0 = cosf(v.x) * cosf(__ldg(theta + k + 0));
    float c1 = cosf(v.y) * cosf(__ldg(theta + k + 1));
    float c2 = cosf(v.z) * cosf(__ldg(theta + k + 2));
    float c3 = cosf(v.w) * cosf(__ldg(theta + k + 3));
    size_t rowbase = ((size_t)(k >> 6) * M_TOK + m) * 64;
    int    col     = (k & 63) ^ (((int)m & 7) << 3);
    __half2 p0 = __floats2half2_rn(c0, c1);
    __half2 p1 = __floats2half2_rn(c2, c3);
    uint2 val;
    val.x = *reinterpret_cast<uint32_t*>(&p0);
    val.y = *reinterpret_cast<uint32_t*>(&p1);
    *reinterpret_cast<uint2*>(q + rowbase + col) = val;
}

__global__ void cvt_w_kernel(const float4* __restrict__ w,
                             __half*       __restrict__ dst,
                             int kshift, int kmask, int R) {
    size_t i4 = (size_t)blockIdx.x * blockDim.x + threadIdx.x;
    size_t i  = i4 * 4;
    int    k  = (int)(i & kmask);
    size_t r  = i >> kshift;
    float4 v  = w[i4];
    size_t rowbase = ((size_t)(k >> 6) * R + r) * 64;
    int    col     = (k & 63) ^ (((int)r & 7) << 3);
    __half2 p0 = __floats2half2_rn(v.x, v.y);
    __half2 p1 = __floats2half2_rn(v.z, v.w);
    uint2 val;
    val.x = *reinterpret_cast<uint32_t*>(&p0);
    val.y = *reinterpret_cast<uint32_t*>(&p1);
    *reinterpret_cast<uint2*>(dst + rowbase + col) = val;
}

// ============================================================================
// GEMM: C[64x128 tile] = A @ B^T, fp16 in, fp32 accum (mma.sync.m16n8k16).
// 128 threads = 4 warps, warp grid 2(m) x 2(n), warp tile 32x64.
// 3-stage cp.async pipeline (depth 2), 3 CTAs per SM.
// EPI==0: relu -> fp16, swizzled tiled layout (feeds GEMM2)
// EPI==1: fp32 row-major [M, DDIM] final output
// ============================================================================
template <int EPI>
__global__ void __launch_bounds__(THREADS, 3)
gemm_hmma_kernel(const __half* __restrict__ A, const __half* __restrict__ B,
                 void* __restrict__ outp, int a_rows, int b_rows, int ktiles) {
    extern __shared__ char smem[];
    const uint32_t sb = smem_u32(smem);

    const int tid  = threadIdx.x;
    const int lane = tid & 31;
    const int wid  = tid >> 5;
    const int wm   = wid & 1;        // 0..1 -> 32-row slab
    const int wn   = wid >> 1;       // 0..1 -> 64-col slab

    const int n0 = blockIdx.x * BN;
    const int m0 = blockIdx.y * BM;

    // ---- A ldmatrix.x4 lane map (R3-proven):
    const int a_r  = (wm * 32) + ((lane >> 3) & 1) * 8 + (lane & 7); // + i*16
    const int a_dc = lane >> 4;                                      // 0/1
    // ---- B ldmatrix.x4 lane map (R10/R13-proven CONTIGUOUS-PAIR dests):
    const int b_r  = (wn * 64) + ((lane >> 4) << 3) + (lane & 7);    // + jp*16
    const int b_dc = (lane >> 3) & 1;                                // 0/1

    // ---- stage-fill source/dst (linear copy of pre-swizzled tiles) ----
    const char* a_src0 = reinterpret_cast<const char*>(A + ((size_t)m0) * 64);
    const char* b_src0 = reinterpret_cast<const char*>(B + ((size_t)n0) * 64);
    const size_t a_kstep = (size_t)a_rows * 128;   // bytes per K-chunk
    const size_t b_kstep = (size_t)b_rows * 128;

    auto load_stage = [&](int kt, int s) {
        const uint32_t sa = sb + s * STAGE_BYTES;
        const char* ag = a_src0 + (size_t)kt * a_kstep;
        const char* bg = b_src0 + (size_t)kt * b_kstep;
        #pragma unroll
        for (int it = 0; it < 4; it++)   // A: 8KB (128 thr x 16B = 2KB/pass)
            cp_async16(sa + tid * 16 + it * 2048, ag + tid * 16 + it * 2048);
        #pragma unroll
        for (int it = 0; it < 8; it++)   // B: 16KB
            cp_async16(sa + A_BYTES + tid * 16 + it * 2048,
                       bg + tid * 16 + it * 2048);
    };

    // ---- prologue: fill STAGES-1 = 2 stages ----
    #pragma unroll
    for (int s = 0; s < STAGES - 1; s++) {
        load_stage(s, s);
        CP_COMMIT();
    }

    float acc[2][8][4];
    #pragma unroll
    for (int i = 0; i < 2; i++)
        #pragma unroll
        for (int j = 0; j < 8; j++)
            #pragma unroll
            for (int e = 0; e < 4; e++) acc[i][j][e] = 0.0f;

    int cons = 0;                       // slot being consumed this iter
    int prod = STAGES - 1;              // slot being filled this iter
    for (int kt = 0; kt < ktiles; kt++) {
        CP_WAIT(STAGES - 2);            // depth-2: tolerate one chunk in flight
        __syncthreads();

        const int kn = kt + STAGES - 1;
        if (kn < ktiles) load_stage(kn, prod);
        CP_COMMIT();

        const uint32_t sa  = sb + cons * STAGE_BYTES;
        const uint32_t sbB = sa + A_BYTES;
        if (++cons == STAGES) cons = 0;
        if (++prod == STAGES) prod = 0;

        #pragma unroll
        for (int k16 = 0; k16 < 4; k16++) {
            const int c0 = k16 * 2;                 // compile-time constant
            uint32_t af[2][4], bf[8][2];
            #pragma unroll
            for (int i = 0; i < 2; i++) {
                const int r = a_r + i * 16;
                const uint32_t addr =
                    sa + r * 128 + (((c0 + a_dc) ^ (r & 7)) << 4);
                ldsm_x4(af[i][0], af[i][1], af[i][2], af[i][3], addr);
            }
            #pragma unroll
            for (int jp = 0; jp < 4; jp++) {        // 2 n-tiles per ldsm_x4
                const int r = b_r + jp * 16;
                const uint32_t addr =
                    sbB + r * 128 + (((c0 + b_dc) ^ (r & 7)) << 4);
                ldsm_x4(bf[2 * jp][0], bf[2 * jp][1],
                        bf[2 * jp + 1][0], bf[2 * jp + 1][1], addr);
            }
            #pragma unroll
            for (int i = 0; i < 2; i++)
                #pragma unroll
                for (int j = 0; j < 8; j++)
                    mma16816(acc[i][j], af[i], bf[j]);
        }
    }

    // ---- epilogue (R15-verified mapping) ----
    const int mrow0 = m0 + wm * 32 + (lane >> 2);
    const int nc0   = wn * 64 + (lane & 3) * 2;

    if (EPI == 0) {
        __half* H = reinterpret_cast<__half*>(outp);
        #pragma unroll
        for (int i = 0; i < 2; i++) {
            #pragma unroll
            for (int j = 0; j < 8; j++) {
                const int f = n0 + nc0 + j * 8;
                #pragma unroll
                for (int half_m = 0; half_m < 2; half_m++) {
                    const int m = mrow0 + i * 16 + half_m * 8;
                    float v0 = fmaxf(acc[i][j][half_m * 2 + 0], 0.0f);
                    float v1 = fmaxf(acc[i][j][half_m * 2 + 1], 0.0f);
                    __half2 hv = __floats2half2_rn(v0, v1);
                    const size_t idx =
                        ((size_t)(f >> 6) * M_TOK + (size_t)m) * 64 +
                        ((f & 63) ^ ((m & 7) << 3));
                    *reinterpret_cast<__half2*>(H + idx) = hv;
                }
            }
        }
    } else {
        float* O = reinterpret_cast<float*>(outp);
        #pragma unroll
        for (int i = 0; i < 2; i++) {
            #pragma unroll
            for (int j = 0; j < 8; j++) {
                const int n = n0 + nc0 + j * 8;
                #pragma unroll
                for (int half_m = 0; half_m < 2; half_m++) {
                    const int m = mrow0 + i * 16 + half_m * 8;
                    float2 fv = make_float2(acc[i][j][half_m * 2 + 0],
                                            acc[i][j][half_m * 2 + 1]);
                    *reinterpret_cast<float2*>(O + (size_t)m * DDIM + n) = fv;
                }
            }
        }
    }
}

// ============================================================================
// kernel_launch
// ============================================================================
extern "C" void kernel_launch(void* const* d_in, const int* in_sizes, int n_in,
                              void* d_out, int out_size) {
    (void)in_sizes; (void)n_in; (void)out_size;
    const float* x  = (const float*)d_in[0];
    const float* th = (const float*)d_in[1];
    const float* W1 = (const float*)d_in[2];
    const float* W2 = (const float*)d_in[3];

    void *qp, *w1p, *w2p, *hp;
    cudaGetSymbolAddress(&qp,  g_q);
    cudaGetSymbolAddress(&w1p, g_w1);
    cudaGetSymbolAddress(&w2p, g_w2);
    cudaGetSymbolAddress(&hp,  g_h);

    cudaFuncSetAttribute(gemm_hmma_kernel<0>,
                         cudaFuncAttributeMaxDynamicSharedMemorySize, SMEM_TOTAL);
    cudaFuncSetAttribute(gemm_hmma_kernel<1>,
                         cudaFuncAttributeMaxDynamicSharedMemorySize, SMEM_TOTAL);

    // 1) quantum feature map + fp16 quantize (tiled/swizzled layout)
    cvt_q_kernel<<<(M_TOK * DDIM) / 4 / 256, 256>>>(
        (const float4*)x, th, (__half*)qp);
    // 2) weight conversions
    cvt_w_kernel<<<(FDIM * DDIM) / 4 / 256, 256>>>(
        (const float4*)W1, (__half*)w1p, 10, DDIM - 1, FDIM);
    cvt_w_kernel<<<(DDIM * FDIM) / 4 / 256, 256>>>(
        (const float4*)W2, (__half*)w2p, 12, FDIM - 1, DDIM);

    // 3) GEMM1: h = relu(q @ W1^T)   M=16384, N=4096, K=1024
    gemm_hmma_kernel<0><<<dim3(FDIM / BN, M_TOK / BM), THREADS, SMEM_TOTAL>>>(
        (const __half*)qp, (const __half*)w1p, hp, M_TOK, FDIM, DDIM / BK);

    // 4) GEMM2: out = h @ W2^T       M=16384, N=1024, K=4096
    gemm_hmma_kernel<1><<<dim3(DDIM / BN, M_TOK / BM), THREADS, SMEM_TOTAL>>>(
        (const __half*)hp, (const __half*)w2p, d_out, M_TOK, DDIM, FDIM / BK);
}

// round 17
// speedup vs baseline: 1.0576x; 1.0576x over previous
#include <cuda_runtime.h>
#include <cuda_fp16.h>
#include <cstdint>

// ============================================================================
// FeedForwardQuantum: x[4,4096,1024], W1[4096,1024], W2[1024,4096]
//   q   = cos(x)*cos(theta)          [M=16384, 1024]  fp16 (pre-swizzled tiles)
//   h   = relu(q @ W1^T)             [M, 4096]        fp16 (pre-swizzled tiles)
//   out = h @ W2^T                   [M, 1024]        fp32 row-major
//
// Plain-sm_100 tensor path: mma.sync.m16n8k16 + ldmatrix + cp.async pipeline.
// R17 = R15 engine EXACTLY (best: 686us, tensor 76.2%):
//   BM=64, BN=128, 128-thr CTAs (4 warps, 2m x 2n, warp tile 32x64),
//   STAGES=2 (48KB/CTA) -> 4 CTAs/SM = 16 warps in 4 barrier domains,
//   contiguous-pair B ldsm_x4, static addressing, regs 128.
// + the three conversion kernels FUSED into one launch (block-range
//   partition): W converts run concurrently with the q convert instead of
//   serializing in 3 launches (~30us -> ~20us of pure memory work).
//
// Staging layout (fp16, GMEM): [K/64 chunks][rows][64 halves], 128B-swizzle
// XOR applied at write time:
//     half_index(row, k) = ((k>>6)*R + row)*64 + ((k&63) ^ ((row&7)<<3))
// ============================================================================
static constexpr int M_TOK = 16384;
static constexpr int DDIM  = 1024;
static constexpr int FDIM  = 4096;

static constexpr int BM = 64;
static constexpr int BN = 128;
static constexpr int BK = 64;          // 64 halves = 128B rows
static constexpr int STAGES = 2;
static constexpr int THREADS = 128;    // 4 warps, grid 2(m) x 2(n), tile 32x64

static constexpr int A_BYTES     = BM * 128;             // 8192
static constexpr int B_BYTES     = BN * 128;             // 16384
static constexpr int STAGE_BYTES = A_BYTES + B_BYTES;    // 24576
static constexpr int SMEM_TOTAL  = STAGES * STAGE_BYTES; // 49152

// fused convert block ranges (256 threads, 4 fp32->fp16 quads per thread)
static constexpr int CVT_Q_BLOCKS  = (M_TOK * DDIM) / 4 / 256;  // 16384
static constexpr int CVT_W1_BLOCKS = (FDIM * DDIM) / 4 / 256;   // 4096
static constexpr int CVT_W2_BLOCKS = (DDIM * FDIM) / 4 / 256;   // 4096
static constexpr int CVT_BLOCKS = CVT_Q_BLOCKS + CVT_W1_BLOCKS + CVT_W2_BLOCKS;

// ---- scratch (device globals; no runtime allocation allowed) ----
__device__ __half g_q [16777216];   // q  tiled/swizzled  [1024/64][16384][64]
__device__ __half g_w1[ 4194304];   // W1 tiled/swizzled  [1024/64][4096 ][64]
__device__ __half g_w2[ 4194304];   // W2 tiled/swizzled  [4096/64][1024 ][64]
__device__ __half g_h [67108864];   // h  tiled/swizzled  [4096/64][16384][64]

// ============================================================================
// PTX helpers
// ============================================================================
__device__ __forceinline__ uint32_t smem_u32(const void* p) {
    uint32_t a;
    asm("{ .reg .u64 t; cvta.to.shared.u64 t, %1; cvt.u32.u64 %0, t; }"
        : "=r"(a) : "l"(p));
    return a;
}

__device__ __forceinline__ void cp_async16(uint32_t dst, const void* src) {
    asm volatile("cp.async.cg.shared.global [%0], [%1], 16;"
                 :: "r"(dst), "l"(src) : "memory");
}
#define CP_COMMIT() asm volatile("cp.async.commit_group;" ::: "memory")
#define CP_WAIT(n)  asm volatile("cp.async.wait_group %0;" :: "n"(n) : "memory")

__device__ __forceinline__ void ldsm_x4(uint32_t& r0, uint32_t& r1,
                                        uint32_t& r2, uint32_t& r3,
                                        uint32_t addr) {
    asm volatile("ldmatrix.sync.aligned.m8n8.x4.shared.b16 {%0,%1,%2,%3}, [%4];"
                 : "=r"(r0), "=r"(r1), "=r"(r2), "=r"(r3) : "r"(addr));
}

__device__ __forceinline__ void mma16816(float* d, const uint32_t* a,
                                         const uint32_t* b) {
    asm volatile(
        "mma.sync.aligned.m16n8k16.row.col.f32.f16.f16.f32 "
        "{%0,%1,%2,%3}, {%4,%5,%6,%7}, {%8,%9}, {%0,%1,%2,%3};"
        : "+f"(d[0]), "+f"(d[1]), "+f"(d[2]), "+f"(d[3])
        : "r"(a[0]), "r"(a[1]), "r"(a[2]), "r"(a[3]), "r"(b[0]), "r"(b[1]));
}

// ============================================================================
// Fused conversion kernel: fp32 -> fp16 into the swizzled tiled layout.
// Block ranges: [0, CVT_Q_BLOCKS) -> q; then W1; then W2.
//   half_index(row, k) = ((k>>6)*R + row)*64 + ((k&63) ^ ((row&7)<<3))
// ============================================================================
__device__ __forceinline__ void cvt_w_body(const float4* __restrict__ w,
                                           __half* __restrict__ dst,
                                           size_t i4, int kshift, int kmask,
                                           int R) {
    size_t i  = i4 * 4;
    int    k  = (int)(i & kmask);
    size_t r  = i >> kshift;
    float4 v  = w[i4];
    size_t rowbase = ((size_t)(k >> 6) * R + r) * 64;
    int    col     = (k & 63) ^ (((int)r & 7) << 3);
    __half2 p0 = __floats2half2_rn(v.x, v.y);
    __half2 p1 = __floats2half2_rn(v.z, v.w);
    uint2 val;
    val.x = *reinterpret_cast<uint32_t*>(&p0);
    val.y = *reinterpret_cast<uint32_t*>(&p1);
    *reinterpret_cast<uint2*>(dst + rowbase + col) = val;
}

__global__ void cvt_all_kernel(const float4* __restrict__ x,
                               const float*  __restrict__ theta,
                               const float4* __restrict__ W1,
                               const float4* __restrict__ W2,
                               __half* __restrict__ q,
                               __half* __restrict__ w1,
                               __half* __restrict__ w2) {
    const int b = blockIdx.x;
    if (b < CVT_Q_BLOCKS) {
        size_t i4 = (size_t)b * blockDim.x + threadIdx.x;
        size_t i  = i4 * 4;
        int    k  = (int)(i & (DDIM - 1));
        size_t m  = i >> 10;
        float4 v  = x[i4];
        float c0 = cosf(v.x) * cosf(__ldg(theta + k + 0));
        float c1 = cosf(v.y) * cosf(__ldg(theta + k + 1));
        float c2 = cosf(v.z) * cosf(__ldg(theta + k + 2));
        float c3 = cosf(v.w) * cosf(__ldg(theta + k + 3));
        size_t rowbase = ((size_t)(k >> 6) * M_TOK + m) * 64;
        int    col     = (k & 63) ^ (((int)m & 7) << 3);
        __half2 p0 = __floats2half2_rn(c0, c1);
        __half2 p1 = __floats2half2_rn(c2, c3);
        uint2 val;
        val.x = *reinterpret_cast<uint32_t*>(&p0);
        val.y = *reinterpret_cast<uint32_t*>(&p1);
        *reinterpret_cast<uint2*>(q + rowbase + col) = val;
    } else if (b < CVT_Q_BLOCKS + CVT_W1_BLOCKS) {
        size_t i4 = (size_t)(b - CVT_Q_BLOCKS) * blockDim.x + threadIdx.x;
        cvt_w_body(W1, w1, i4, 10, DDIM - 1, FDIM);
    } else {
        size_t i4 = (size_t)(b - CVT_Q_BLOCKS - CVT_W1_BLOCKS) * blockDim.x
                    + threadIdx.x;
        cvt_w_body(W2, w2, i4, 12, FDIM - 1, DDIM);
    }
}

// ============================================================================
// GEMM: C[64x128 tile] = A @ B^T, fp16 in, fp32 accum (mma.sync.m16n8k16).
// 128 threads = 4 warps, warp grid 2(m) x 2(n), warp tile 32x64.
// 2-stage cp.async pipeline, 4 CTAs per SM (16 warps, 4 barrier domains).
// EPI==0: relu -> fp16, swizzled tiled layout (feeds GEMM2)
// EPI==1: fp32 row-major [M, DDIM] final output
// ============================================================================
template <int EPI>
__global__ void __launch_bounds__(THREADS, 4)
gemm_hmma_kernel(const __half* __restrict__ A, const __half* __restrict__ B,
                 void* __restrict__ outp, int a_rows, int b_rows, int ktiles) {
    extern __shared__ char smem[];
    const uint32_t sb = smem_u32(smem);

    const int tid  = threadIdx.x;
    const int lane = tid & 31;
    const int wid  = tid >> 5;
    const int wm   = wid & 1;        // 0..1 -> 32-row slab
    const int wn   = wid >> 1;       // 0..1 -> 64-col slab

    const int n0 = blockIdx.x * BN;
    const int m0 = blockIdx.y * BM;

    // ---- A ldmatrix.x4 lane map (R3-proven):
    const int a_r  = (wm * 32) + ((lane >> 3) & 1) * 8 + (lane & 7); // + i*16
    const int a_dc = lane >> 4;                                      // 0/1
    // ---- B ldmatrix.x4 lane map (R10/R13-proven CONTIGUOUS-PAIR dests):
    const int b_r  = (wn * 64) + ((lane >> 4) << 3) + (lane & 7);    // + jp*16
    const int b_dc = (lane >> 3) & 1;                                // 0/1

    // ---- stage-fill source/dst (linear copy of pre-swizzled tiles) ----
    const char* a_src0 = reinterpret_cast<const char*>(A + ((size_t)m0) * 64);
    const char* b_src0 = reinterpret_cast<const char*>(B + ((size_t)n0) * 64);
    const size_t a_kstep = (size_t)a_rows * 128;   // bytes per K-chunk
    const size_t b_kstep = (size_t)b_rows * 128;

    auto load_stage = [&](int kt, int s) {
        const uint32_t sa = sb + s * STAGE_BYTES;
        const char* ag = a_src0 + (size_t)kt * a_kstep;
        const char* bg = b_src0 + (size_t)kt * b_kstep;
        #pragma unroll
        for (int it = 0; it < 4; it++)   // A: 8KB (128 thr x 16B = 2KB/pass)
            cp_async16(sa + tid * 16 + it * 2048, ag + tid * 16 + it * 2048);
        #pragma unroll
        for (int it = 0; it < 8; it++)   // B: 16KB
            cp_async16(sa + A_BYTES + tid * 16 + it * 2048,
                       bg + tid * 16 + it * 2048);
    };

    // ---- prologue: fill 1 stage ----
    load_stage(0, 0);
    CP_COMMIT();

    float acc[2][8][4];
    #pragma unroll
    for (int i = 0; i < 2; i++)
        #pragma unroll
        for (int j = 0; j < 8; j++)
            #pragma unroll
            for (int e = 0; e < 4; e++) acc[i][j][e] = 0.0f;

    for (int kt = 0; kt < ktiles; kt++) {
        CP_WAIT(0);
        __syncthreads();

        const int kn = kt + 1;
        if (kn < ktiles) load_stage(kn, kn & 1);
        CP_COMMIT();

        const uint32_t sa  = sb + (kt & 1) * STAGE_BYTES;
        const uint32_t sbB = sa + A_BYTES;

        #pragma unroll
        for (int k16 = 0; k16 < 4; k16++) {
            const int c0 = k16 * 2;                 // compile-time constant
            uint32_t af[2][4], bf[8][2];
            #pragma unroll
            for (int i = 0; i < 2; i++) {
                const int r = a_r + i * 16;
                const uint32_t addr =
                    sa + r * 128 + (((c0 + a_dc) ^ (r & 7)) << 4);
                ldsm_x4(af[i][0], af[i][1], af[i][2], af[i][3], addr);
            }
            #pragma unroll
            for (int jp = 0; jp < 4; jp++) {        // 2 n-tiles per ldsm_x4
                const int r = b_r + jp * 16;
                const uint32_t addr =
                    sbB + r * 128 + (((c0 + b_dc) ^ (r & 7)) << 4);
                ldsm_x4(bf[2 * jp][0], bf[2 * jp][1],
                        bf[2 * jp + 1][0], bf[2 * jp + 1][1], addr);
            }
            #pragma unroll
            for (int i = 0; i < 2; i++)
                #pragma unroll
                for (int j = 0; j < 8; j++)
                    mma16816(acc[i][j], af[i], bf[j]);
        }
    }

    // ---- epilogue (R15-verified mapping) ----
    const int mrow0 = m0 + wm * 32 + (lane >> 2);
    const int nc0   = wn * 64 + (lane & 3) * 2;

    if (EPI == 0) {
        __half* H = reinterpret_cast<__half*>(outp);
        #pragma unroll
        for (int i = 0; i < 2; i++) {
            #pragma unroll
            for (int j = 0; j < 8; j++) {
                const int f = n0 + nc0 + j * 8;
                #pragma unroll
                for (int half_m = 0; half_m < 2; half_m++) {
                    const int m = mrow0 + i * 16 + half_m * 8;
                    float v0 = fmaxf(acc[i][j][half_m * 2 + 0], 0.0f);
                    float v1 = fmaxf(acc[i][j][half_m * 2 + 1], 0.0f);
                    __half2 hv = __floats2half2_rn(v0, v1);
                    const size_t idx =
                        ((size_t)(f >> 6) * M_TOK + (size_t)m) * 64 +
                        ((f & 63) ^ ((m & 7) << 3));
                    *reinterpret_cast<__half2*>(H + idx) = hv;
                }
            }
        }
    } else {
        float* O = reinterpret_cast<float*>(outp);
        #pragma unroll
        for (int i = 0; i < 2; i++) {
            #pragma unroll
            for (int j = 0; j < 8; j++) {
                const int n = n0 + nc0 + j * 8;
                #pragma unroll
                for (int half_m = 0; half_m < 2; half_m++) {
                    const int m = mrow0 + i * 16 + half_m * 8;
                    float2 fv = make_float2(acc[i][j][half_m * 2 + 0],
                                            acc[i][j][half_m * 2 + 1]);
                    *reinterpret_cast<float2*>(O + (size_t)m * DDIM + n) = fv;
                }
            }
        }
    }
}

// ============================================================================
// kernel_launch
// ============================================================================
extern "C" void kernel_launch(void* const* d_in, const int* in_sizes, int n_in,
                              void* d_out, int out_size) {
    (void)in_sizes; (void)n_in; (void)out_size;
    const float* x  = (const float*)d_in[0];
    const float* th = (const float*)d_in[1];
    const float* W1 = (const float*)d_in[2];
    const float* W2 = (const float*)d_in[3];

    void *qp, *w1p, *w2p, *hp;
    cudaGetSymbolAddress(&qp,  g_q);
    cudaGetSymbolAddress(&w1p, g_w1);
    cudaGetSymbolAddress(&w2p, g_w2);
    cudaGetSymbolAddress(&hp,  g_h);

    cudaFuncSetAttribute(gemm_hmma_kernel<0>,
                         cudaFuncAttributeMaxDynamicSharedMemorySize, SMEM_TOTAL);
    cudaFuncSetAttribute(gemm_hmma_kernel<1>,
                         cudaFuncAttributeMaxDynamicSharedMemorySize, SMEM_TOTAL);

    // 1) fused conversions: q feature map + W1 + W2 in ONE launch
    cvt_all_kernel<<<CVT_BLOCKS, 256>>>(
        (const float4*)x, th, (const float4*)W1, (const float4*)W2,
        (__half*)qp, (__half*)w1p, (__half*)w2p);

    // 2) GEMM1: h = relu(q @ W1^T)   M=16384, N=4096, K=1024
    gemm_hmma_kernel<0><<<dim3(FDIM / BN, M_TOK / BM), THREADS, SMEM_TOTAL>>>(
        (const __half*)qp, (const __half*)w1p, hp, M_TOK, FDIM, DDIM / BK);

    // 3) GEMM2: out = h @ W2^T       M=16384, N=1024, K=4096
    gemm_hmma_kernel<1><<<dim3(DDIM / BN, M_TOK / BM), THREADS, SMEM_TOTAL>>>(
        (const __half*)hp, (const __half*)w2p, d_out, M_TOK, DDIM, FDIM / BK);
}